// round 13
// baseline (speedup 1.0000x reference)
#include <cuda_runtime.h>
#include <cuda_fp16.h>
#include <cstdint>

#define NB   64
#define LDEC 256
#define TENC 512
#define DK   512
#define DV   512
#define NVOC 10000
#define LSTM_BLOCKS 128
#define N_WORKERS 168
#define K5_TILES (128 * 16)
#define K7_NT 79
#define K7_TILES (128 * K7_NT)

// ---------------- static device scratch ----------------
__device__ __half g_keyh[TENC * NB * DK];
__device__ __half g_valT[(size_t)NB * DV * TENC];    // (n,v,t) fp16
__device__ __half g_Ain[(size_t)LDEC * NB * 1024];   // row (l*64+n): [ce | ctx]
__device__ __half g_A7[(size_t)LDEC * NB * 1024];    // row (l*64+n): [h2 | val]
__device__ float  g_E[(size_t)NB * LDEC * TENC];
__device__ __half g_att[(size_t)NB * LDEC * TENC];
__device__ float  g_Zin1[(size_t)LDEC * NB * 2048];
__device__ __half g_wih1[2048 * 1024];
__device__ __half g_whh1[2048 * 512];
__device__ __half g_wih2h[2048 * 512];
__device__ __half g_whh2h[2048 * 512];
__device__ __half g_wout[(size_t)NVOC * 1024];
__device__ float  g_b1[2048];
__device__ float  g_b2[2048];
__device__ __half g_h1[2][NB * 512];
__device__ __half g_h2[2][NB * 512];
__device__ unsigned g_bar_cnt;
__device__ int g_qS, g_q4, g_q5, g_q7;
__device__ int g_doneS[128];
__device__ int g_done4[2];
__device__ int g_k5done[128];

// ---------------- helpers ----------------
__device__ __forceinline__ uint32_t smcvt(const void *p) {
    return (uint32_t)__cvta_generic_to_shared(p);
}
__device__ __forceinline__ void cpa16(uint32_t dst, const void *src, int bytes) {
    asm volatile("cp.async.cg.shared.global [%0], [%1], 16, %2;\n"
                 :: "r"(dst), "l"(src), "r"(bytes));
}
__device__ __forceinline__ void cpcommit() { asm volatile("cp.async.commit_group;\n"); }
template <int N> __device__ __forceinline__ void cpwait() {
    asm volatile("cp.async.wait_group %0;\n" :: "n"(N));
}
__device__ __forceinline__ void ldsm4(uint32_t &r0, uint32_t &r1, uint32_t &r2, uint32_t &r3,
                                      const void *p) {
    uint32_t a = smcvt(p);
    asm volatile("ldmatrix.sync.aligned.m8n8.x4.shared.b16 {%0,%1,%2,%3},[%4];"
                 : "=r"(r0), "=r"(r1), "=r"(r2), "=r"(r3) : "r"(a));
}
__device__ __forceinline__ void mma16816(float *c, const uint32_t *a, uint32_t b0, uint32_t b1) {
    asm volatile(
        "mma.sync.aligned.m16n8k16.row.col.f32.f16.f16.f32 "
        "{%0,%1,%2,%3},{%4,%5,%6,%7},{%8,%9},{%0,%1,%2,%3};"
        : "+f"(c[0]), "+f"(c[1]), "+f"(c[2]), "+f"(c[3])
        : "r"(a[0]), "r"(a[1]), "r"(a[2]), "r"(a[3]), "r"(b0), "r"(b1));
}

// ============ generic GEMM tile: C[m,nn] = sum_k A[m,k]*B[nn,k] (+bias) ============
__device__ __forceinline__ void do_tile(
    const __half *A, long long lda, const __half *B, long long ldb, int kt,
    float *Cf, __half *Ch, const float *bias, int Ncols,
    int m0, int n0, int rsh, int rmask, long long ldl, long long ldn,
    __half *As, __half *Bs, int tid, int lane, int wid) {
    const int wm = wid & 3, wn = wid >> 2;
    const int row = tid >> 1;
    const int rs7 = row & 7;
    float acc[2][8][4];
#pragma unroll
    for (int i = 0; i < 2; i++)
#pragma unroll
        for (int j = 0; j < 8; j++)
#pragma unroll
            for (int e = 0; e < 4; e++) acc[i][j][e] = 0.f;

    const int gn = n0 + row;
    const __half *bsrcrow = B + (size_t)(gn < Ncols ? gn : Ncols - 1) * ldb;
    const int bbytes = (gn < Ncols) ? 16 : 0;
    const __half *asrcrow = A + (size_t)(m0 + row) * lda;

#define WISSUE(st, kc)                                                          \
    {                                                                           \
        _Pragma("unroll") for (int i = 0; i < 4; i++) {                         \
            int c8 = (tid & 1) * 4 + i;                                         \
            int sw = (c8 ^ rs7) * 8;                                            \
            cpa16(smcvt(As + (st)*8192 + row * 64 + sw), asrcrow + (kc)*64 + c8 * 8, 16); \
            cpa16(smcvt(Bs + (st)*8192 + row * 64 + sw), bsrcrow + (kc)*64 + c8 * 8, bbytes); \
        }                                                                       \
    }

    WISSUE(0, 0); cpcommit();
    WISSUE(1, 1); cpcommit();
    for (int kc = 0; kc < kt; kc++) {
        int st = kc % 3;
        cpwait<1>();
        __syncthreads();
        if (kc + 2 < kt) { WISSUE((kc + 2) % 3, kc + 2); }
        cpcommit();
#pragma unroll
        for (int kk = 0; kk < 64; kk += 16) {
            uint32_t a[2][4], bb[4][4];
#pragma unroll
            for (int mt = 0; mt < 2; mt++) {
                int r = wm * 32 + mt * 16 + (lane & 15);
                int ch = (kk >> 3) + (lane >> 4);
                ldsm4(a[mt][0], a[mt][1], a[mt][2], a[mt][3],
                      As + st * 8192 + r * 64 + ((ch ^ (r & 7)) * 8));
            }
#pragma unroll
            for (int bt = 0; bt < 4; bt++) {
                int r = wn * 64 + bt * 16 + (lane & 15);
                int ch = (kk >> 3) + (lane >> 4);
                ldsm4(bb[bt][0], bb[bt][1], bb[bt][2], bb[bt][3],
                      Bs + st * 8192 + r * 64 + ((ch ^ (r & 7)) * 8));
            }
#pragma unroll
            for (int mt = 0; mt < 2; mt++)
#pragma unroll
                for (int nt = 0; nt < 8; nt++) {
                    int bt = nt >> 1, j = nt & 1;
                    mma16816(acc[mt][nt], a[mt], bb[bt][j], bb[bt][j + 2]);
                }
        }
    }
#undef WISSUE
#pragma unroll
    for (int mt = 0; mt < 2; mt++)
#pragma unroll
        for (int nt = 0; nt < 8; nt++)
#pragma unroll
            for (int h = 0; h < 2; h++) {
                int m = m0 + wm * 32 + mt * 16 + (lane >> 2) + h * 8;
                int nn = n0 + wn * 64 + nt * 8 + (lane & 3) * 2;
                float v0 = acc[mt][nt][h * 2 + 0];
                float v1 = acc[mt][nt][h * 2 + 1];
                size_t addr = (size_t)(m >> rsh) * ldl + (size_t)(m & rmask) * ldn + nn;
                if (nn + 1 < Ncols) {
                    if (Cf) {
                        if (bias) { v0 += bias[nn]; v1 += bias[nn + 1]; }
                        *(float2 *)(Cf + addr) = make_float2(v0, v1);
                    } else {
                        *(__half2 *)(Ch + addr) = __floats2half2_rn(v0, v1);
                    }
                } else if (nn < Ncols) {
                    if (Cf) Cf[addr] = v0 + (bias ? bias[nn] : 0.f);
                    else Ch[addr] = __float2half(v0);
                }
            }
}

// ---------------- LSTM (128 blocks x 4 units, ALL 8 warps) ----------------
// acc[4]: per-warp 16(M) x 8(N) fragment; block computes 64 x 16.
__device__ __forceinline__ void lstm_mm(float acc[4], const __half *src,
                                        const __half *Ws, __half *As,
                                        int tid, int lane, int wm, int wn) {
#define LISSUE(st, c)                                                          \
    for (int q = tid; q < 1024; q += 256) {                                    \
        int r = q >> 4, c8 = q & 15;                                           \
        cpa16(smcvt(As + (st)*8704 + r * 136 + c8 * 8),                        \
              src + (size_t)r * 512 + (c)*128 + c8 * 8, 16);                   \
    }
    LISSUE(0, 0); cpcommit();
    for (int c = 0; c < 4; c++) {
        int st = c & 1;
        if (c + 1 < 4) { LISSUE(st ^ 1, c + 1); }
        cpcommit();
        cpwait<1>();
        __syncthreads();
#pragma unroll
        for (int kk = 0; kk < 128; kk += 16) {
            uint32_t a[4], b[4];
            ldsm4(a[0], a[1], a[2], a[3],
                  As + st * 8704 + (wm * 16 + (lane & 15)) * 136 + kk + (lane >> 4) * 8);
            ldsm4(b[0], b[1], b[2], b[3],
                  Ws + (size_t)(lane & 15) * 520 + c * 128 + kk + (lane >> 4) * 8);
            mma16816(acc, a, b[wn], b[wn + 2]);
        }
        __syncthreads();
    }
#undef LISSUE
}

__device__ __forceinline__ void store_zs(float acc[4], float *zs,
                                         int lane, int wm, int wn) {
#pragma unroll
    for (int e = 0; e < 4; e++) {
        int m = wm * 16 + (lane >> 2) + (e >> 1) * 8;
        int col = wn * 8 + (lane & 3) * 2 + (e & 1);
        zs[m * 17 + col] = acc[e];
    }
    __syncthreads();
}

__device__ __forceinline__ void bar_arrive(int tid) {
    __threadfence();
    __syncthreads();
    if (tid == 0) atomicAdd(&g_bar_cnt, 1u);
}
__device__ __forceinline__ void bar_wait(unsigned target, int tid) {
    if (tid == 0) {
        while (*(volatile unsigned *)&g_bar_cnt < target) {}
        __threadfence();
    }
    __syncthreads();
}

__device__ void lstm_path(char *smraw) {
    const int tid = threadIdx.x, lane = tid & 31, wid = tid >> 5;
    __half *Ws1 = (__half *)smraw;                 // [16][520]
    __half *Ws2a = Ws1 + 16 * 520;
    __half *Ws2b = Ws2a + 16 * 520;
    __half *As = Ws2b + 16 * 520;                  // [2][64][136]
    float *zs = (float *)(As + 2 * 64 * 136);      // [64][17]
    float *cs1 = zs + 64 * 17;                     // [256]
    float *cs2 = cs1 + 256;

    const int wm = wid & 3, wn = wid >> 2;         // 8 warps: 4x2 of 16x8
    const int u0 = blockIdx.x * 4;

    for (int q = tid; q < 16 * 64; q += 256) {
        int r = q >> 6, c8 = q & 63;
        size_t grow = (size_t)((r >> 2) * 512 + u0 + (r & 3)) * 512;
        *(uint4 *)&Ws1[r * 520 + c8 * 8] = *(const uint4 *)(g_whh1 + grow + c8 * 8);
        *(uint4 *)&Ws2a[r * 520 + c8 * 8] = *(const uint4 *)(g_wih2h + grow + c8 * 8);
        *(uint4 *)&Ws2b[r * 520 + c8 * 8] = *(const uint4 *)(g_whh2h + grow + c8 * 8);
    }
    if (tid < 256) { cs1[tid] = 0.f; cs2[tid] = 0.f; }
    __syncthreads();

    unsigned tgt = 0;
    for (int t = 0; t < LDEC; t++) {
        int cur = t & 1, nxt = cur ^ 1;
        float acc[4];
#pragma unroll
        for (int e = 0; e < 4; e++) acc[e] = 0.f;

        lstm_mm(acc, &g_h1[cur][0], Ws1, As, tid, lane, wm, wn);
        store_zs(acc, zs, lane, wm, wn);
        if (tid == 0) {
            while (*(volatile int *)&g_k5done[t >> 1] < 16) __nanosleep(64);
            __threadfence();
        }
        __syncthreads();
        {
            int n = tid & 63, ul = tid >> 6;
            float zi = zs[n * 17 + ul], zf = zs[n * 17 + 4 + ul];
            float zg = zs[n * 17 + 8 + ul], zo = zs[n * 17 + 12 + ul];
            int u = u0 + ul;
            const float *zr = g_Zin1 + ((size_t)t * 64 + n) * 2048;
            zi += zr[u]; zf += zr[512 + u]; zg += zr[1024 + u]; zo += zr[1536 + u];
            float c = cs1[n * 4 + ul];
            float ig = 1.f / (1.f + expf(-zi));
            float fg = 1.f / (1.f + expf(-zf));
            float og = 1.f / (1.f + expf(-zo));
            float cn = fg * c + ig * tanhf(zg);
            float h = og * tanhf(cn);
            cs1[n * 4 + ul] = cn;
            __stcg(&g_h1[nxt][n * 512 + u], __float2half(h));
        }
        bar_arrive(tid); tgt++;
        unsigned tA = tgt;

#pragma unroll
        for (int e = 0; e < 4; e++) acc[e] = 0.f;
        if (t > 0) bar_wait((tgt - 1) * LSTM_BLOCKS, tid);
        lstm_mm(acc, &g_h2[cur][0], Ws2b, As, tid, lane, wm, wn);
        bar_wait(tA * LSTM_BLOCKS, tid);
        lstm_mm(acc, &g_h1[nxt][0], Ws2a, As, tid, lane, wm, wn);
        store_zs(acc, zs, lane, wm, wn);
        {
            int n = tid & 63, ul = tid >> 6;
            float zi = zs[n * 17 + ul], zf = zs[n * 17 + 4 + ul];
            float zg = zs[n * 17 + 8 + ul], zo = zs[n * 17 + 12 + ul];
            int u = u0 + ul;
            zi += g_b2[u]; zf += g_b2[512 + u]; zg += g_b2[1024 + u]; zo += g_b2[1536 + u];
            float c = cs2[n * 4 + ul];
            float ig = 1.f / (1.f + expf(-zi));
            float fg = 1.f / (1.f + expf(-zf));
            float og = 1.f / (1.f + expf(-zo));
            float cn = fg * c + ig * tanhf(zg);
            float h = og * tanhf(cn);
            cs2[n * 4 + ul] = cn;
            __stcg(&g_h2[nxt][n * 512 + u], __float2half(h));
            g_A7[((size_t)t * 64 + n) * 1024 + u] = __float2half(h);
        }
        bar_arrive(tid); tgt++;
    }
}

// ---------------- K7 worker ----------------
__device__ __noinline__ void worker_k7(__half *smh, float *out, const float *b_out) {
    __half *As = smh;
    __half *Bs = smh + 3 * 8192;
    __shared__ int s_q7;
    const int tid = threadIdx.x, lane = tid & 31, wid = tid >> 5;
    for (;;) {
        __syncthreads();
        if (tid == 0) s_q7 = atomicAdd(&g_q7, 1);
        __syncthreads();
        int q = s_q7;
        if (q >= K7_TILES) break;
        int mx = q / K7_NT, ny = q % K7_NT;
        if (tid == 0) {
            unsigned need = (4u * mx + 4u) * LSTM_BLOCKS;
            while (*(volatile unsigned *)&g_bar_cnt < need) __nanosleep(64);
            __threadfence();
        }
        __syncthreads();
        do_tile(g_A7, 1024, g_wout, 1024, 16, out, nullptr, b_out, NVOC,
                mx * 128, ny * 128, 6, 63, NVOC, (long long)LDEC * NVOC,
                As, Bs, tid, lane, wid);
    }
}

// ============ mega kernel: softmax + K4 + K5 + LSTM + K7 ============
__global__ void __launch_bounds__(256, 2) mega_k(float *out, const float *b_out,
                                                 const int *lens) {
    extern __shared__ __half smh[];
    __half *As = smh;
    __half *Bs = smh + 3 * 8192;
    __shared__ int s_q;
    const int tid = threadIdx.x, lane = tid & 31, wid = tid >> 5;

    // ---- phase S: masked softmax (128 chunks of 128 rows) ----
    for (;;) {
        __syncthreads();
        if (tid == 0) s_q = atomicAdd(&g_qS, 1);
        __syncthreads();
        int c = s_q;
        if (c >= 128) break;
        int n = c >> 1;
        int len = lens[n];
        size_t base = (size_t)n * 256 + (size_t)(c & 1) * 128;
        for (int r = wid; r < 128; r += 8) {
            const float *e = g_E + (base + r) * 512;
            float v[16], m = -1e30f;
#pragma unroll
            for (int i = 0; i < 16; i++) {
                v[i] = e[lane + i * 32];
                m = fmaxf(m, v[i]);
            }
#pragma unroll
            for (int o = 16; o; o >>= 1) m = fmaxf(m, __shfl_xor_sync(0xffffffffu, m, o));
            float s = 0.f;
#pragma unroll
            for (int i = 0; i < 16; i++) {
                int t = lane + i * 32;
                float ex = (t < len) ? expf(v[i] - m) : 0.f;
                v[i] = ex;
                s += ex;
            }
#pragma unroll
            for (int o = 16; o; o >>= 1) s += __shfl_xor_sync(0xffffffffu, s, o);
            float inv = 1.f / s;
            __half *ao = g_att + (base + r) * 512;
#pragma unroll
            for (int i = 0; i < 16; i++) ao[lane + i * 32] = __float2half(v[i] * inv);
        }
        __threadfence();
        __syncthreads();
        if (tid == 0) atomicExch(&g_doneS[c], 1);
    }

    // ---- phase K4: mx-major so done4[0] completes early ----
    for (;;) {
        __syncthreads();
        if (tid == 0) s_q = atomicAdd(&g_q4, 1);
        __syncthreads();
        int q = s_q;
        if (q >= 512) break;
        int mx = q >> 8, n = (q >> 2) & 63, ny = q & 3;
        if (tid == 0) {
            while (*(volatile int *)&g_doneS[n * 2 + mx] == 0) __nanosleep(64);
            __threadfence();
        }
        __syncthreads();
        do_tile(g_att + (size_t)n * 131072, 512, g_valT + (size_t)n * 262144, 512, 8,
                nullptr, g_Ain + (size_t)n * 1024 + 512, nullptr, 512,
                mx * 128, ny * 128, 0, 0, 65536, 0, As, Bs, tid, lane, wid);
        __threadfence();
        __syncthreads();
        if (tid == 0) atomicAdd(&g_done4[mx], 1);
    }

    if (blockIdx.x < LSTM_BLOCKS) {
        lstm_path((char *)smh);
        __syncthreads();
        worker_k7(smh, out, b_out);
    } else {
        // ---- K5: Zin1 = Ain @ wih1^T + b1, gated on K4 halves ----
        for (;;) {
            __syncthreads();
            if (tid == 0) s_q = atomicAdd(&g_q5, 1);
            __syncthreads();
            int q = s_q;
            if (q >= K5_TILES) break;
            int mx = q >> 4, ny = q & 15;
            if (tid == 0) {
                while (*(volatile int *)&g_done4[mx >> 6] < 256) __nanosleep(64);
                __threadfence();
            }
            __syncthreads();
            do_tile(g_Ain, 1024, g_wih1, 1024, 16, g_Zin1, nullptr, g_b1, 2048,
                    mx * 128, ny * 128, 0, 0, 2048, 0, As, Bs, tid, lane, wid);
            __threadfence();
            __syncthreads();
            if (tid == 0) atomicAdd(&g_k5done[mx], 1);
        }
        worker_k7(smh, out, b_out);
    }
}

// ============ K2: energy E[(n,l),t] = CE . key ============
__global__ void __launch_bounds__(256, 2) k2_k() {
    extern __shared__ __half smh[];
    const int b = blockIdx.x, tid = threadIdx.x, lane = tid & 31, wid = tid >> 5;
    int n = b >> 3, mx = (b >> 2) & 1, ny = b & 3;
    do_tile(g_Ain + (size_t)n * 1024, 65536, g_keyh + (size_t)n * 512, 32768, 8,
            g_E + (size_t)n * 131072, nullptr, nullptr, 512,
            mx * 128, ny * 128, 0, 0, 512, 0,
            smh, smh + 3 * 8192, tid, lane, wid);
}

// ============ prep ============
__device__ __forceinline__ void f2h_seg(const float *s, __half *d, int n8,
                                        int gt, int gs) {
    const float4 *s4 = (const float4 *)s;
    uint4 *d4 = (uint4 *)d;
    for (int i = gt; i < n8; i += gs) {
        float4 a = s4[i * 2], b = s4[i * 2 + 1];
        __half2 h0 = __floats2half2_rn(a.x, a.y);
        __half2 h1 = __floats2half2_rn(a.z, a.w);
        __half2 h2 = __floats2half2_rn(b.x, b.y);
        __half2 h3 = __floats2half2_rn(b.z, b.w);
        d4[i] = make_uint4(*(uint32_t *)&h0, *(uint32_t *)&h1,
                           *(uint32_t *)&h2, *(uint32_t *)&h3);
    }
}

__global__ void prep_k(const float *key, const int *text, const float *emb,
                       const float *b_ih1, const float *b_hh1,
                       const float *b_ih2, const float *b_hh2,
                       const float *w_ih1, const float *w_hh1,
                       const float *w_ih2, const float *w_hh2,
                       const float *w_out, const float *values) {
    __shared__ float tile[32][33];
    const int gt = blockIdx.x * 256 + threadIdx.x;
    const int gs = gridDim.x * 256;

    f2h_seg(key, g_keyh, 2097152, gt, gs);
    f2h_seg(w_ih1, g_wih1, 262144, gt, gs);
    f2h_seg(w_hh1, g_whh1, 131072, gt, gs);
    f2h_seg(w_ih2, g_wih2h, 131072, gt, gs);
    f2h_seg(w_hh2, g_whh2h, 131072, gt, gs);
    f2h_seg(w_out, g_wout, 1280000, gt, gs);

    for (int j = gt; j < 2097152; j += gs) {
        int k4 = (j & 127) * 4;
        int r = j >> 7;
        int n = r & 63, l = r >> 6;
        int tok = text[n * LDEC + l];
        float4 v = *(const float4 *)(emb + (size_t)tok * 512 + k4);
        __half2 h0 = __floats2half2_rn(v.x, v.y);
        __half2 h1 = __floats2half2_rn(v.z, v.w);
        *(uint2 *)(g_Ain + (size_t)r * 1024 + k4) =
            make_uint2(*(uint32_t *)&h0, *(uint32_t *)&h1);
    }
    for (int j = gt; j < 1048576; j += gs) {
        int e8 = j * 8;
        int col = e8 & 511;
        int r = e8 >> 9;
        int n = r & 63, l = r >> 6;
        const float4 *s = (const float4 *)(values + (size_t)l * 32768 + n * 512 + col);
        float4 a = s[0], b = s[1];
        __half2 h0 = __floats2half2_rn(a.x, a.y);
        __half2 h1 = __floats2half2_rn(a.z, a.w);
        __half2 h2 = __floats2half2_rn(b.x, b.y);
        __half2 h3 = __floats2half2_rn(b.z, b.w);
        *(uint4 *)(g_A7 + (size_t)r * 1024 + 512 + col) =
            make_uint4(*(uint32_t *)&h0, *(uint32_t *)&h1,
                       *(uint32_t *)&h2, *(uint32_t *)&h3);
    }
    for (int j = gt; j < 2048; j += gs) {
        g_b1[j] = b_ih1[j] + b_hh1[j];
        g_b2[j] = b_ih2[j] + b_hh2[j];
    }
    for (int j = gt; j < NB * 512; j += gs) {
        g_h1[0][j] = __ushort_as_half((unsigned short)0);
        g_h2[0][j] = __ushort_as_half((unsigned short)0);
    }
    if (gt == 0) {
        g_bar_cnt = 0; g_qS = 0; g_q4 = 0; g_q5 = 0; g_q7 = 0;
        g_done4[0] = 0; g_done4[1] = 0;
    }
    for (int j = gt; j < 128; j += gs) { g_k5done[j] = 0; g_doneS[j] = 0; }

    const int tx = threadIdx.x & 31, ty = threadIdx.x >> 5;
    for (int t = blockIdx.x; t < 16384; t += gridDim.x) {
        int n = t >> 8, vb = (t >> 4) & 15, tb = t & 15;
        int t0 = tb * 32, v0 = vb * 32;
        __syncthreads();
#pragma unroll
        for (int i = 0; i < 4; i++)
            tile[ty + i * 8][tx] =
                values[(size_t)(t0 + ty + i * 8) * 32768 + n * 512 + v0 + tx];
        __syncthreads();
#pragma unroll
        for (int i = 0; i < 4; i++)
            g_valT[((size_t)n * 512 + v0 + ty + i * 8) * 512 + t0 + tx] =
                __float2half(tile[tx][ty + i * 8]);
    }
}

// ---------------- host ----------------
static const int GEMM_SMEM = 3 * (8192 + 8192) * 2;  // 96 KB

extern "C" void kernel_launch(void *const *d_in, const int *in_sizes, int n_in,
                              void *d_out, int out_size) {
    const float *key = (const float *)d_in[0];
    const float *values = (const float *)d_in[1];
    const int *text = (const int *)d_in[2];
    const int *text_lens = (const int *)d_in[3];
    const float *emb = (const float *)d_in[4];
    const float *w_ih1 = (const float *)d_in[5];
    const float *w_hh1 = (const float *)d_in[6];
    const float *b_ih1 = (const float *)d_in[7];
    const float *b_hh1 = (const float *)d_in[8];
    const float *w_ih2 = (const float *)d_in[9];
    const float *w_hh2 = (const float *)d_in[10];
    const float *b_ih2 = (const float *)d_in[11];
    const float *b_hh2 = (const float *)d_in[12];
    const float *w_out = (const float *)d_in[13];
    const float *b_out = (const float *)d_in[14];
    float *out = (float *)d_out;

    cudaFuncSetAttribute(k2_k, cudaFuncAttributeMaxDynamicSharedMemorySize, GEMM_SMEM);
    cudaFuncSetAttribute(mega_k, cudaFuncAttributeMaxDynamicSharedMemorySize, GEMM_SMEM);

    // 1) all prep in one launch
    prep_k<<<2048, 256>>>(key, text, emb, b_ih1, b_hh1, b_ih2, b_hh2,
                          w_ih1, w_hh1, w_ih2, w_hh2, w_out, values);

    // 2) K2 energy GEMM (full-chip wave)
    k2_k<<<512, 256, GEMM_SMEM>>>();

    // 3) mega: softmax + K4 + K5 + persistent LSTM + K7
    mega_k<<<LSTM_BLOCKS + N_WORKERS, 256, GEMM_SMEM>>>(out, b_out, text_lens);
}

// round 14
// speedup vs baseline: 1.1101x; 1.1101x over previous
#include <cuda_runtime.h>
#include <cuda_fp16.h>
#include <cstdint>

#define NB   64
#define LDEC 256
#define TENC 512
#define DK   512
#define DV   512
#define NVOC 10000
#define LSTM_BLOCKS 128
#define N_WORKERS 168
#define K5_TILES (128 * 16)
#define K7_NT 79
#define K7_TILES (128 * K7_NT)

// ---------------- static device scratch ----------------
__device__ __half g_keyh[TENC * NB * DK];
__device__ __half g_valT[(size_t)NB * DV * TENC];    // (n,v,t) fp16
__device__ __half g_Ain[(size_t)LDEC * NB * 1024];   // row (l*64+n): [ce | ctx]
__device__ __half g_A7[(size_t)LDEC * NB * 1024];    // row (l*64+n): [h2 | val]
__device__ float  g_E[(size_t)NB * LDEC * TENC];
__device__ __half g_att[(size_t)NB * LDEC * TENC];
__device__ float  g_Zin1[(size_t)LDEC * NB * 2048];
__device__ __half g_wih1[2048 * 1024];
__device__ __half g_whh1[2048 * 512];
__device__ __half g_wih2h[2048 * 512];
__device__ __half g_whh2h[2048 * 512];
__device__ __half g_wout[(size_t)NVOC * 1024];
__device__ float  g_b1[2048];
__device__ float  g_b2[2048];
__device__ __half g_h1[2][NB * 512];
__device__ __half g_h2[2][NB * 512];
__device__ unsigned g_bar_cnt;
__device__ int g_qS, g_q4, g_q5, g_q7;
__device__ int g_doneS[128];
__device__ int g_done4[2];
__device__ int g_k5done[128];

// ---------------- helpers ----------------
__device__ __forceinline__ uint32_t smcvt(const void *p) {
    return (uint32_t)__cvta_generic_to_shared(p);
}
__device__ __forceinline__ void cpa16(uint32_t dst, const void *src, int bytes) {
    asm volatile("cp.async.cg.shared.global [%0], [%1], 16, %2;\n"
                 :: "r"(dst), "l"(src), "r"(bytes));
}
__device__ __forceinline__ void cpcommit() { asm volatile("cp.async.commit_group;\n"); }
template <int N> __device__ __forceinline__ void cpwait() {
    asm volatile("cp.async.wait_group %0;\n" :: "n"(N));
}
__device__ __forceinline__ void ldsm4(uint32_t &r0, uint32_t &r1, uint32_t &r2, uint32_t &r3,
                                      const void *p) {
    uint32_t a = smcvt(p);
    asm volatile("ldmatrix.sync.aligned.m8n8.x4.shared.b16 {%0,%1,%2,%3},[%4];"
                 : "=r"(r0), "=r"(r1), "=r"(r2), "=r"(r3) : "r"(a));
}
__device__ __forceinline__ void mma16816(float *c, const uint32_t *a, uint32_t b0, uint32_t b1) {
    asm volatile(
        "mma.sync.aligned.m16n8k16.row.col.f32.f16.f16.f32 "
        "{%0,%1,%2,%3},{%4,%5,%6,%7},{%8,%9},{%0,%1,%2,%3};"
        : "+f"(c[0]), "+f"(c[1]), "+f"(c[2]), "+f"(c[3])
        : "r"(a[0]), "r"(a[1]), "r"(a[2]), "r"(a[3]), "r"(b0), "r"(b1));
}
__device__ __forceinline__ void nbar() {
    asm volatile("bar.sync 1, 128;" ::: "memory");
}

// ============ generic GEMM tile: C[m,nn] = sum_k A[m,k]*B[nn,k] (+bias) ============
__device__ __forceinline__ void do_tile(
    const __half *A, long long lda, const __half *B, long long ldb, int kt,
    float *Cf, __half *Ch, const float *bias, int Ncols,
    int m0, int n0, int rsh, int rmask, long long ldl, long long ldn,
    __half *As, __half *Bs, int tid, int lane, int wid) {
    const int wm = wid & 3, wn = wid >> 2;
    const int row = tid >> 1;
    const int rs7 = row & 7;
    float acc[2][8][4];
#pragma unroll
    for (int i = 0; i < 2; i++)
#pragma unroll
        for (int j = 0; j < 8; j++)
#pragma unroll
            for (int e = 0; e < 4; e++) acc[i][j][e] = 0.f;

    const int gn = n0 + row;
    const __half *bsrcrow = B + (size_t)(gn < Ncols ? gn : Ncols - 1) * ldb;
    const int bbytes = (gn < Ncols) ? 16 : 0;
    const __half *asrcrow = A + (size_t)(m0 + row) * lda;

#define WISSUE(st, kc)                                                          \
    {                                                                           \
        _Pragma("unroll") for (int i = 0; i < 4; i++) {                         \
            int c8 = (tid & 1) * 4 + i;                                         \
            int sw = (c8 ^ rs7) * 8;                                            \
            cpa16(smcvt(As + (st)*8192 + row * 64 + sw), asrcrow + (kc)*64 + c8 * 8, 16); \
            cpa16(smcvt(Bs + (st)*8192 + row * 64 + sw), bsrcrow + (kc)*64 + c8 * 8, bbytes); \
        }                                                                       \
    }

    WISSUE(0, 0); cpcommit();
    WISSUE(1, 1); cpcommit();
    for (int kc = 0; kc < kt; kc++) {
        int st = kc % 3;
        cpwait<1>();
        __syncthreads();
        if (kc + 2 < kt) { WISSUE((kc + 2) % 3, kc + 2); }
        cpcommit();
#pragma unroll
        for (int kk = 0; kk < 64; kk += 16) {
            uint32_t a[2][4], bb[4][4];
#pragma unroll
            for (int mt = 0; mt < 2; mt++) {
                int r = wm * 32 + mt * 16 + (lane & 15);
                int ch = (kk >> 3) + (lane >> 4);
                ldsm4(a[mt][0], a[mt][1], a[mt][2], a[mt][3],
                      As + st * 8192 + r * 64 + ((ch ^ (r & 7)) * 8));
            }
#pragma unroll
            for (int bt = 0; bt < 4; bt++) {
                int r = wn * 64 + bt * 16 + (lane & 15);
                int ch = (kk >> 3) + (lane >> 4);
                ldsm4(bb[bt][0], bb[bt][1], bb[bt][2], bb[bt][3],
                      Bs + st * 8192 + r * 64 + ((ch ^ (r & 7)) * 8));
            }
#pragma unroll
            for (int mt = 0; mt < 2; mt++)
#pragma unroll
                for (int nt = 0; nt < 8; nt++) {
                    int bt = nt >> 1, j = nt & 1;
                    mma16816(acc[mt][nt], a[mt], bb[bt][j], bb[bt][j + 2]);
                }
        }
    }
#undef WISSUE
#pragma unroll
    for (int mt = 0; mt < 2; mt++)
#pragma unroll
        for (int nt = 0; nt < 8; nt++)
#pragma unroll
            for (int h = 0; h < 2; h++) {
                int m = m0 + wm * 32 + mt * 16 + (lane >> 2) + h * 8;
                int nn = n0 + wn * 64 + nt * 8 + (lane & 3) * 2;
                float v0 = acc[mt][nt][h * 2 + 0];
                float v1 = acc[mt][nt][h * 2 + 1];
                size_t addr = (size_t)(m >> rsh) * ldl + (size_t)(m & rmask) * ldn + nn;
                if (nn + 1 < Ncols) {
                    if (Cf) {
                        if (bias) { v0 += bias[nn]; v1 += bias[nn + 1]; }
                        *(float2 *)(Cf + addr) = make_float2(v0, v1);
                    } else {
                        *(__half2 *)(Ch + addr) = __floats2half2_rn(v0, v1);
                    }
                } else if (nn < Ncols) {
                    if (Cf) Cf[addr] = v0 + (bias ? bias[nn] : 0.f);
                    else Ch[addr] = __float2half(v0);
                }
            }
}

// ---------------- LSTM (128 blocks x 4 units, warps 0-3) ----------------
__device__ __forceinline__ void lstm_mm(float acc[2][4], const __half *src,
                                        const __half *Ws, __half *As,
                                        int tid, int lane, int wm, int wn) {
#define LISSUE(st, c)                                                          \
    for (int q = tid; q < 1024; q += 128) {                                    \
        int r = q >> 4, c8 = q & 15;                                           \
        cpa16(smcvt(As + (st)*8704 + r * 136 + c8 * 8),                        \
              src + (size_t)r * 512 + (c)*128 + c8 * 8, 16);                   \
    }
    LISSUE(0, 0); cpcommit();
    for (int c = 0; c < 4; c++) {
        int st = c & 1;
        if (c + 1 < 4) { LISSUE(st ^ 1, c + 1); }
        cpcommit();
        cpwait<1>();
        nbar();
#pragma unroll
        for (int kk = 0; kk < 128; kk += 16) {
            uint32_t a[2][4], b[4];
#pragma unroll
            for (int mt = 0; mt < 2; mt++)
                ldsm4(a[mt][0], a[mt][1], a[mt][2], a[mt][3],
                      As + st * 8704 + (wm * 32 + mt * 16 + (lane & 15)) * 136 +
                          kk + (lane >> 4) * 8);
            ldsm4(b[0], b[1], b[2], b[3],
                  Ws + (size_t)(lane & 15) * 520 + c * 128 + kk + (lane >> 4) * 8);
#pragma unroll
            for (int mt = 0; mt < 2; mt++)
                mma16816(acc[mt], a[mt], b[wn], b[wn + 2]);
        }
        nbar();
    }
#undef LISSUE
}

__device__ __forceinline__ void store_zs(float acc[2][4], float *zs,
                                         int lane, int wm, int wn) {
#pragma unroll
    for (int mt = 0; mt < 2; mt++)
#pragma unroll
        for (int e = 0; e < 4; e++) {
            int m = wm * 32 + mt * 16 + (lane >> 2) + (e >> 1) * 8;
            int col = wn * 8 + (lane & 3) * 2 + (e & 1);
            zs[m * 17 + col] = acc[mt][e];
        }
    nbar();
}

__device__ __forceinline__ void bar_arrive(int tid) {
    __threadfence();
    nbar();
    if (tid == 0) atomicAdd(&g_bar_cnt, 1u);
}
__device__ __forceinline__ void bar_wait(unsigned target, int tid) {
    if (tid == 0) {
        while (*(volatile unsigned *)&g_bar_cnt < target) {}
        __threadfence();
    }
    nbar();
}

__device__ void lstm_path(char *smraw) {
    const int tid = threadIdx.x, lane = tid & 31, wid = tid >> 5;
    if (wid >= 4) return;
    __half *Ws1 = (__half *)smraw;                 // [16][520]
    __half *Ws2a = Ws1 + 16 * 520;
    __half *Ws2b = Ws2a + 16 * 520;
    __half *As = Ws2b + 16 * 520;                  // [2][64][136]
    float *zs = (float *)(As + 2 * 64 * 136);      // [64][17]
    float *cs1 = zs + 64 * 17;                     // [256]
    float *cs2 = cs1 + 256;

    const int wm = wid & 1, wn = wid >> 1;
    const int u0 = blockIdx.x * 4;

    for (int q = tid; q < 16 * 64; q += 128) {
        int r = q >> 6, c8 = q & 63;
        size_t grow = (size_t)((r >> 2) * 512 + u0 + (r & 3)) * 512;
        *(uint4 *)&Ws1[r * 520 + c8 * 8] = *(const uint4 *)(g_whh1 + grow + c8 * 8);
        *(uint4 *)&Ws2a[r * 520 + c8 * 8] = *(const uint4 *)(g_wih2h + grow + c8 * 8);
        *(uint4 *)&Ws2b[r * 520 + c8 * 8] = *(const uint4 *)(g_whh2h + grow + c8 * 8);
    }
    for (int q = tid; q < 256; q += 128) { cs1[q] = 0.f; cs2[q] = 0.f; }
    nbar();

    unsigned tgt = 0;
    for (int t = 0; t < LDEC; t++) {
        int cur = t & 1, nxt = cur ^ 1;
        float acc[2][4];
#pragma unroll
        for (int i = 0; i < 2; i++)
#pragma unroll
            for (int e = 0; e < 4; e++) acc[i][e] = 0.f;

        lstm_mm(acc, &g_h1[cur][0], Ws1, As, tid, lane, wm, wn);
        store_zs(acc, zs, lane, wm, wn);
        if (tid == 0) {
            while (*(volatile int *)&g_k5done[t >> 1] < 16) __nanosleep(64);
            __threadfence();
        }
        nbar();
#pragma unroll
        for (int i = 0; i < 2; i++) {
            int idx = tid + i * 128;
            int n = idx & 63, ul = idx >> 6;
            float zi = zs[n * 17 + ul], zf = zs[n * 17 + 4 + ul];
            float zg = zs[n * 17 + 8 + ul], zo = zs[n * 17 + 12 + ul];
            int u = u0 + ul;
            const float *zr = g_Zin1 + ((size_t)t * 64 + n) * 2048;
            zi += zr[u]; zf += zr[512 + u]; zg += zr[1024 + u]; zo += zr[1536 + u];
            float c = cs1[n * 4 + ul];
            float ig = 1.f / (1.f + expf(-zi));
            float fg = 1.f / (1.f + expf(-zf));
            float og = 1.f / (1.f + expf(-zo));
            float cn = fg * c + ig * tanhf(zg);
            float h = og * tanhf(cn);
            cs1[n * 4 + ul] = cn;
            __stcg(&g_h1[nxt][n * 512 + u], __float2half(h));
        }
        bar_arrive(tid); tgt++;
        unsigned tA = tgt;

#pragma unroll
        for (int i = 0; i < 2; i++)
#pragma unroll
            for (int e = 0; e < 4; e++) acc[i][e] = 0.f;
        if (t > 0) bar_wait((tgt - 1) * LSTM_BLOCKS, tid);
        lstm_mm(acc, &g_h2[cur][0], Ws2b, As, tid, lane, wm, wn);
        bar_wait(tA * LSTM_BLOCKS, tid);
        lstm_mm(acc, &g_h1[nxt][0], Ws2a, As, tid, lane, wm, wn);
        store_zs(acc, zs, lane, wm, wn);
#pragma unroll
        for (int i = 0; i < 2; i++) {
            int idx = tid + i * 128;
            int n = idx & 63, ul = idx >> 6;
            float zi = zs[n * 17 + ul], zf = zs[n * 17 + 4 + ul];
            float zg = zs[n * 17 + 8 + ul], zo = zs[n * 17 + 12 + ul];
            int u = u0 + ul;
            zi += g_b2[u]; zf += g_b2[512 + u]; zg += g_b2[1024 + u]; zo += g_b2[1536 + u];
            float c = cs2[n * 4 + ul];
            float ig = 1.f / (1.f + expf(-zi));
            float fg = 1.f / (1.f + expf(-zf));
            float og = 1.f / (1.f + expf(-zo));
            float cn = fg * c + ig * tanhf(zg);
            float h = og * tanhf(cn);
            cs2[n * 4 + ul] = cn;
            __stcg(&g_h2[nxt][n * 512 + u], __float2half(h));
            g_A7[((size_t)t * 64 + n) * 1024 + u] = __float2half(h);
        }
        bar_arrive(tid); tgt++;
    }
}

// ---------------- K7 worker ----------------
__device__ __noinline__ void worker_k7(__half *smh, float *out, const float *b_out) {
    __half *As = smh;
    __half *Bs = smh + 3 * 8192;
    __shared__ int s_q7;
    const int tid = threadIdx.x, lane = tid & 31, wid = tid >> 5;
    for (;;) {
        __syncthreads();
        if (tid == 0) s_q7 = atomicAdd(&g_q7, 1);
        __syncthreads();
        int q = s_q7;
        if (q >= K7_TILES) break;
        int mx = q / K7_NT, ny = q % K7_NT;
        if (tid == 0) {
            unsigned need = (4u * mx + 4u) * LSTM_BLOCKS;
            while (*(volatile unsigned *)&g_bar_cnt < need) __nanosleep(64);
            __threadfence();
        }
        __syncthreads();
        do_tile(g_A7, 1024, g_wout, 1024, 16, out, nullptr, b_out, NVOC,
                mx * 128, ny * 128, 6, 63, NVOC, (long long)LDEC * NVOC,
                As, Bs, tid, lane, wid);
    }
}

// ============ mega kernel: softmax + K4 + K5 + LSTM + K7 ============
__global__ void __launch_bounds__(256, 2) mega_k(float *out, const float *b_out,
                                                 const int *lens) {
    extern __shared__ __half smh[];
    __half *As = smh;
    __half *Bs = smh + 3 * 8192;
    __shared__ int s_q;
    const int tid = threadIdx.x, lane = tid & 31, wid = tid >> 5;

    // ---- phase S: masked softmax (128 chunks of 128 rows) ----
    for (;;) {
        __syncthreads();
        if (tid == 0) s_q = atomicAdd(&g_qS, 1);
        __syncthreads();
        int c = s_q;
        if (c >= 128) break;
        int n = c >> 1;
        int len = lens[n];
        size_t base = (size_t)n * 256 + (size_t)(c & 1) * 128;
        for (int r = wid; r < 128; r += 8) {
            const float *e = g_E + (base + r) * 512;
            float v[16], m = -1e30f;
#pragma unroll
            for (int i = 0; i < 16; i++) {
                v[i] = e[lane + i * 32];
                m = fmaxf(m, v[i]);
            }
#pragma unroll
            for (int o = 16; o; o >>= 1) m = fmaxf(m, __shfl_xor_sync(0xffffffffu, m, o));
            float s = 0.f;
#pragma unroll
            for (int i = 0; i < 16; i++) {
                int t = lane + i * 32;
                float ex = (t < len) ? expf(v[i] - m) : 0.f;
                v[i] = ex;
                s += ex;
            }
#pragma unroll
            for (int o = 16; o; o >>= 1) s += __shfl_xor_sync(0xffffffffu, s, o);
            float inv = 1.f / s;
            __half *ao = g_att + (base + r) * 512;
#pragma unroll
            for (int i = 0; i < 16; i++) ao[lane + i * 32] = __float2half(v[i] * inv);
        }
        __threadfence();
        __syncthreads();
        if (tid == 0) atomicExch(&g_doneS[c], 1);
    }

    // ---- phase K4: mx-major so done4[0] completes early ----
    for (;;) {
        __syncthreads();
        if (tid == 0) s_q = atomicAdd(&g_q4, 1);
        __syncthreads();
        int q = s_q;
        if (q >= 512) break;
        int mx = q >> 8, n = (q >> 2) & 63, ny = q & 3;
        if (tid == 0) {
            while (*(volatile int *)&g_doneS[n * 2 + mx] == 0) __nanosleep(64);
            __threadfence();
        }
        __syncthreads();
        do_tile(g_att + (size_t)n * 131072, 512, g_valT + (size_t)n * 262144, 512, 8,
                nullptr, g_Ain + (size_t)n * 1024 + 512, nullptr, 512,
                mx * 128, ny * 128, 0, 0, 65536, 0, As, Bs, tid, lane, wid);
        __threadfence();
        __syncthreads();
        if (tid == 0) atomicAdd(&g_done4[mx], 1);
    }

    if (blockIdx.x < LSTM_BLOCKS) {
        lstm_path((char *)smh);
        __syncthreads();
        worker_k7(smh, out, b_out);
    } else {
        // ---- K5: Zin1 = Ain @ wih1^T + b1, gated on K4 halves ----
        for (;;) {
            __syncthreads();
            if (tid == 0) s_q = atomicAdd(&g_q5, 1);
            __syncthreads();
            int q = s_q;
            if (q >= K5_TILES) break;
            int mx = q >> 4, ny = q & 15;
            if (tid == 0) {
                while (*(volatile int *)&g_done4[mx >> 6] < 256) __nanosleep(64);
                __threadfence();
            }
            __syncthreads();
            do_tile(g_Ain, 1024, g_wih1, 1024, 16, g_Zin1, nullptr, g_b1, 2048,
                    mx * 128, ny * 128, 0, 0, 2048, 0, As, Bs, tid, lane, wid);
            __threadfence();
            __syncthreads();
            if (tid == 0) atomicAdd(&g_k5done[mx], 1);
        }
        worker_k7(smh, out, b_out);
    }
}

// ============ K2: energy E[(n,l),t] = CE . key ============
__global__ void __launch_bounds__(256, 2) k2_k() {
    extern __shared__ __half smh[];
    const int b = blockIdx.x, tid = threadIdx.x, lane = tid & 31, wid = tid >> 5;
    int n = b >> 3, mx = (b >> 2) & 1, ny = b & 3;
    do_tile(g_Ain + (size_t)n * 1024, 65536, g_keyh + (size_t)n * 512, 32768, 8,
            g_E + (size_t)n * 131072, nullptr, nullptr, 512,
            mx * 128, ny * 128, 0, 0, 512, 0,
            smh, smh + 3 * 8192, tid, lane, wid);
}

// ============ prep ============
__device__ __forceinline__ void f2h_seg(const float *s, __half *d, int n8,
                                        int gt, int gs) {
    const float4 *s4 = (const float4 *)s;
    uint4 *d4 = (uint4 *)d;
    for (int i = gt; i < n8; i += gs) {
        float4 a = s4[i * 2], b = s4[i * 2 + 1];
        __half2 h0 = __floats2half2_rn(a.x, a.y);
        __half2 h1 = __floats2half2_rn(a.z, a.w);
        __half2 h2 = __floats2half2_rn(b.x, b.y);
        __half2 h3 = __floats2half2_rn(b.z, b.w);
        d4[i] = make_uint4(*(uint32_t *)&h0, *(uint32_t *)&h1,
                           *(uint32_t *)&h2, *(uint32_t *)&h3);
    }
}

__global__ void prep_k(const float *key, const int *text, const float *emb,
                       const float *b_ih1, const float *b_hh1,
                       const float *b_ih2, const float *b_hh2,
                       const float *w_ih1, const float *w_hh1,
                       const float *w_ih2, const float *w_hh2,
                       const float *w_out, const float *values) {
    __shared__ float tile[32][33];
    const int gt = blockIdx.x * 256 + threadIdx.x;
    const int gs = gridDim.x * 256;

    f2h_seg(key, g_keyh, 2097152, gt, gs);
    f2h_seg(w_ih1, g_wih1, 262144, gt, gs);
    f2h_seg(w_hh1, g_whh1, 131072, gt, gs);
    f2h_seg(w_ih2, g_wih2h, 131072, gt, gs);
    f2h_seg(w_hh2, g_whh2h, 131072, gt, gs);
    f2h_seg(w_out, g_wout, 1280000, gt, gs);

    for (int j = gt; j < 2097152; j += gs) {
        int k4 = (j & 127) * 4;
        int r = j >> 7;
        int n = r & 63, l = r >> 6;
        int tok = text[n * LDEC + l];
        float4 v = *(const float4 *)(emb + (size_t)tok * 512 + k4);
        __half2 h0 = __floats2half2_rn(v.x, v.y);
        __half2 h1 = __floats2half2_rn(v.z, v.w);
        *(uint2 *)(g_Ain + (size_t)r * 1024 + k4) =
            make_uint2(*(uint32_t *)&h0, *(uint32_t *)&h1);
    }
    for (int j = gt; j < 1048576; j += gs) {
        int e8 = j * 8;
        int col = e8 & 511;
        int r = e8 >> 9;
        int n = r & 63, l = r >> 6;
        const float4 *s = (const float4 *)(values + (size_t)l * 32768 + n * 512 + col);
        float4 a = s[0], b = s[1];
        __half2 h0 = __floats2half2_rn(a.x, a.y);
        __half2 h1 = __floats2half2_rn(a.z, a.w);
        __half2 h2 = __floats2half2_rn(b.x, b.y);
        __half2 h3 = __floats2half2_rn(b.z, b.w);
        *(uint4 *)(g_A7 + (size_t)r * 1024 + 512 + col) =
            make_uint4(*(uint32_t *)&h0, *(uint32_t *)&h1,
                       *(uint32_t *)&h2, *(uint32_t *)&h3);
    }
    for (int j = gt; j < 2048; j += gs) {
        g_b1[j] = b_ih1[j] + b_hh1[j];
        g_b2[j] = b_ih2[j] + b_hh2[j];
    }
    for (int j = gt; j < NB * 512; j += gs) {
        g_h1[0][j] = __ushort_as_half((unsigned short)0);
        g_h2[0][j] = __ushort_as_half((unsigned short)0);
    }
    if (gt == 0) {
        g_bar_cnt = 0; g_qS = 0; g_q4 = 0; g_q5 = 0; g_q7 = 0;
        g_done4[0] = 0; g_done4[1] = 0;
    }
    for (int j = gt; j < 128; j += gs) { g_k5done[j] = 0; g_doneS[j] = 0; }

    const int tx = threadIdx.x & 31, ty = threadIdx.x >> 5;
    for (int t = blockIdx.x; t < 16384; t += gridDim.x) {
        int n = t >> 8, vb = (t >> 4) & 15, tb = t & 15;
        int t0 = tb * 32, v0 = vb * 32;
        __syncthreads();
#pragma unroll
        for (int i = 0; i < 4; i++)
            tile[ty + i * 8][tx] =
                values[(size_t)(t0 + ty + i * 8) * 32768 + n * 512 + v0 + tx];
        __syncthreads();
#pragma unroll
        for (int i = 0; i < 4; i++)
            g_valT[((size_t)n * 512 + v0 + ty + i * 8) * 512 + t0 + tx] =
                __float2half(tile[tx][ty + i * 8]);
    }
}

// ---------------- host ----------------
static const int GEMM_SMEM = 3 * (8192 + 8192) * 2;  // 96 KB

extern "C" void kernel_launch(void *const *d_in, const int *in_sizes, int n_in,
                              void *d_out, int out_size) {
    const float *key = (const float *)d_in[0];
    const float *values = (const float *)d_in[1];
    const int *text = (const int *)d_in[2];
    const int *text_lens = (const int *)d_in[3];
    const float *emb = (const float *)d_in[4];
    const float *w_ih1 = (const float *)d_in[5];
    const float *w_hh1 = (const float *)d_in[6];
    const float *b_ih1 = (const float *)d_in[7];
    const float *b_hh1 = (const float *)d_in[8];
    const float *w_ih2 = (const float *)d_in[9];
    const float *w_hh2 = (const float *)d_in[10];
    const float *b_ih2 = (const float *)d_in[11];
    const float *b_hh2 = (const float *)d_in[12];
    const float *w_out = (const float *)d_in[13];
    const float *b_out = (const float *)d_in[14];
    float *out = (float *)d_out;

    cudaFuncSetAttribute(k2_k, cudaFuncAttributeMaxDynamicSharedMemorySize, GEMM_SMEM);
    cudaFuncSetAttribute(mega_k, cudaFuncAttributeMaxDynamicSharedMemorySize, GEMM_SMEM);

    // 1) all prep in one launch
    prep_k<<<2048, 256>>>(key, text, emb, b_ih1, b_hh1, b_ih2, b_hh2,
                          w_ih1, w_hh1, w_ih2, w_hh2, w_out, values);

    // 2) K2 energy GEMM (full-chip wave)
    k2_k<<<512, 256, GEMM_SMEM>>>();

    // 3) mega: softmax + K4 + K5 + persistent LSTM + K7
    mega_k<<<LSTM_BLOCKS + N_WORKERS, 256, GEMM_SMEM>>>(out, b_out, text_lens);
}

// round 15
// speedup vs baseline: 1.1112x; 1.0010x over previous
#include <cuda_runtime.h>
#include <cuda_fp16.h>
#include <cstdint>

#define NB   64
#define LDEC 256
#define TENC 512
#define DK   512
#define DV   512
#define NVOC 10000
#define LSTM_BLOCKS 128
#define N_WORKERS 168
#define K5_TILES (128 * 16)
#define K7_NT 79
#define K7_TILES (128 * K7_NT)

// ---------------- static device scratch ----------------
__device__ __half g_keyh[TENC * NB * DK];
__device__ __half g_valT[(size_t)NB * DV * TENC];    // (n,v,t) fp16
__device__ __half g_Ain[(size_t)LDEC * NB * 1024];   // row (l*64+n): [ce | ctx]
__device__ __half g_A7[(size_t)LDEC * NB * 1024];    // row (l*64+n): [h2 | val]
__device__ float  g_E[(size_t)NB * LDEC * TENC];
__device__ __half g_att[(size_t)NB * LDEC * TENC];
__device__ float  g_Zin1[(size_t)LDEC * NB * 2048];
__device__ __half g_wih1[2048 * 1024];
__device__ __half g_whh1[2048 * 512];
__device__ __half g_wih2h[2048 * 512];
__device__ __half g_whh2h[2048 * 512];
__device__ __half g_wout[(size_t)NVOC * 1024];
__device__ float  g_b1[2048];
__device__ float  g_b2[2048];
__device__ __half g_h1[2][NB * 512];
__device__ __half g_h2[2][NB * 512];
__device__ unsigned g_bar_cnt;
__device__ int g_qS, g_q4, g_q5, g_q7;
__device__ int g_doneS[128];
__device__ int g_done4[2];
__device__ int g_k5done[128];

// ---------------- helpers ----------------
__device__ __forceinline__ uint32_t smcvt(const void *p) {
    return (uint32_t)__cvta_generic_to_shared(p);
}
__device__ __forceinline__ void cpa16(uint32_t dst, const void *src, int bytes) {
    asm volatile("cp.async.cg.shared.global [%0], [%1], 16, %2;\n"
                 :: "r"(dst), "l"(src), "r"(bytes));
}
__device__ __forceinline__ void cpcommit() { asm volatile("cp.async.commit_group;\n"); }
template <int N> __device__ __forceinline__ void cpwait() {
    asm volatile("cp.async.wait_group %0;\n" :: "n"(N));
}
__device__ __forceinline__ void ldsm4(uint32_t &r0, uint32_t &r1, uint32_t &r2, uint32_t &r3,
                                      const void *p) {
    uint32_t a = smcvt(p);
    asm volatile("ldmatrix.sync.aligned.m8n8.x4.shared.b16 {%0,%1,%2,%3},[%4];"
                 : "=r"(r0), "=r"(r1), "=r"(r2), "=r"(r3) : "r"(a));
}
__device__ __forceinline__ void mma16816(float *c, const uint32_t *a, uint32_t b0, uint32_t b1) {
    asm volatile(
        "mma.sync.aligned.m16n8k16.row.col.f32.f16.f16.f32 "
        "{%0,%1,%2,%3},{%4,%5,%6,%7},{%8,%9},{%0,%1,%2,%3};"
        : "+f"(c[0]), "+f"(c[1]), "+f"(c[2]), "+f"(c[3])
        : "r"(a[0]), "r"(a[1]), "r"(a[2]), "r"(a[3]), "r"(b0), "r"(b1));
}
__device__ __forceinline__ void nbar() {
    asm volatile("bar.sync 1, 128;" ::: "memory");
}

// ============ generic GEMM tile: C[m,nn] = sum_k A[m,k]*B[nn,k] (+bias) ============
__device__ __forceinline__ void do_tile(
    const __half *A, long long lda, const __half *B, long long ldb, int kt,
    float *Cf, __half *Ch, const float *bias, int Ncols,
    int m0, int n0, int rsh, int rmask, long long ldl, long long ldn,
    __half *As, __half *Bs, int tid, int lane, int wid) {
    const int wm = wid & 3, wn = wid >> 2;
    const int row = tid >> 1;
    const int rs7 = row & 7;
    float acc[2][8][4];
#pragma unroll
    for (int i = 0; i < 2; i++)
#pragma unroll
        for (int j = 0; j < 8; j++)
#pragma unroll
            for (int e = 0; e < 4; e++) acc[i][j][e] = 0.f;

    const int gn = n0 + row;
    const __half *bsrcrow = B + (size_t)(gn < Ncols ? gn : Ncols - 1) * ldb;
    const int bbytes = (gn < Ncols) ? 16 : 0;
    const __half *asrcrow = A + (size_t)(m0 + row) * lda;

#define WISSUE(st, kc)                                                          \
    {                                                                           \
        _Pragma("unroll") for (int i = 0; i < 4; i++) {                         \
            int c8 = (tid & 1) * 4 + i;                                         \
            int sw = (c8 ^ rs7) * 8;                                            \
            cpa16(smcvt(As + (st)*8192 + row * 64 + sw), asrcrow + (kc)*64 + c8 * 8, 16); \
            cpa16(smcvt(Bs + (st)*8192 + row * 64 + sw), bsrcrow + (kc)*64 + c8 * 8, bbytes); \
        }                                                                       \
    }

    WISSUE(0, 0); cpcommit();
    WISSUE(1, 1); cpcommit();
    for (int kc = 0; kc < kt; kc++) {
        int st = kc % 3;
        cpwait<1>();
        __syncthreads();
        if (kc + 2 < kt) { WISSUE((kc + 2) % 3, kc + 2); }
        cpcommit();
#pragma unroll
        for (int kk = 0; kk < 64; kk += 16) {
            uint32_t a[2][4], bb[4][4];
#pragma unroll
            for (int mt = 0; mt < 2; mt++) {
                int r = wm * 32 + mt * 16 + (lane & 15);
                int ch = (kk >> 3) + (lane >> 4);
                ldsm4(a[mt][0], a[mt][1], a[mt][2], a[mt][3],
                      As + st * 8192 + r * 64 + ((ch ^ (r & 7)) * 8));
            }
#pragma unroll
            for (int bt = 0; bt < 4; bt++) {
                int r = wn * 64 + bt * 16 + (lane & 15);
                int ch = (kk >> 3) + (lane >> 4);
                ldsm4(bb[bt][0], bb[bt][1], bb[bt][2], bb[bt][3],
                      Bs + st * 8192 + r * 64 + ((ch ^ (r & 7)) * 8));
            }
#pragma unroll
            for (int mt = 0; mt < 2; mt++)
#pragma unroll
                for (int nt = 0; nt < 8; nt++) {
                    int bt = nt >> 1, j = nt & 1;
                    mma16816(acc[mt][nt], a[mt], bb[bt][j], bb[bt][j + 2]);
                }
        }
    }
#undef WISSUE
#pragma unroll
    for (int mt = 0; mt < 2; mt++)
#pragma unroll
        for (int nt = 0; nt < 8; nt++)
#pragma unroll
            for (int h = 0; h < 2; h++) {
                int m = m0 + wm * 32 + mt * 16 + (lane >> 2) + h * 8;
                int nn = n0 + wn * 64 + nt * 8 + (lane & 3) * 2;
                float v0 = acc[mt][nt][h * 2 + 0];
                float v1 = acc[mt][nt][h * 2 + 1];
                size_t addr = (size_t)(m >> rsh) * ldl + (size_t)(m & rmask) * ldn + nn;
                if (nn + 1 < Ncols) {
                    if (Cf) {
                        if (bias) { v0 += bias[nn]; v1 += bias[nn + 1]; }
                        *(float2 *)(Cf + addr) = make_float2(v0, v1);
                    } else {
                        *(__half2 *)(Ch + addr) = __floats2half2_rn(v0, v1);
                    }
                } else if (nn < Ncols) {
                    if (Cf) Cf[addr] = v0 + (bias ? bias[nn] : 0.f);
                    else Ch[addr] = __float2half(v0);
                }
            }
}

// ---------------- LSTM (128 blocks x 4 units, warps 0-3) ----------------
__device__ __forceinline__ void lstm_mm(float acc[2][4], const __half *src,
                                        const __half *Ws, __half *As,
                                        int tid, int lane, int wm, int wn) {
#define LISSUE(st, c)                                                          \
    for (int q = tid; q < 1024; q += 128) {                                    \
        int r = q >> 4, c8 = q & 15;                                           \
        cpa16(smcvt(As + (st)*8704 + r * 136 + c8 * 8),                        \
              src + (size_t)r * 512 + (c)*128 + c8 * 8, 16);                   \
    }
    LISSUE(0, 0); cpcommit();
    for (int c = 0; c < 4; c++) {
        int st = c & 1;
        if (c + 1 < 4) { LISSUE(st ^ 1, c + 1); }
        cpcommit();
        cpwait<1>();
        nbar();
#pragma unroll
        for (int kk = 0; kk < 128; kk += 16) {
            uint32_t a[2][4], b[4];
#pragma unroll
            for (int mt = 0; mt < 2; mt++)
                ldsm4(a[mt][0], a[mt][1], a[mt][2], a[mt][3],
                      As + st * 8704 + (wm * 32 + mt * 16 + (lane & 15)) * 136 +
                          kk + (lane >> 4) * 8);
            ldsm4(b[0], b[1], b[2], b[3],
                  Ws + (size_t)(lane & 15) * 520 + c * 128 + kk + (lane >> 4) * 8);
#pragma unroll
            for (int mt = 0; mt < 2; mt++)
                mma16816(acc[mt], a[mt], b[wn], b[wn + 2]);
        }
        nbar();
    }
#undef LISSUE
}

__device__ __forceinline__ void store_zs(float acc[2][4], float *zs,
                                         int lane, int wm, int wn) {
#pragma unroll
    for (int mt = 0; mt < 2; mt++)
#pragma unroll
        for (int e = 0; e < 4; e++) {
            int m = wm * 32 + mt * 16 + (lane >> 2) + (e >> 1) * 8;
            int col = wn * 8 + (lane & 3) * 2 + (e & 1);
            zs[m * 17 + col] = acc[mt][e];
        }
    nbar();
}

__device__ __forceinline__ void bar_arrive(int tid) {
    __threadfence();
    nbar();
    if (tid == 0) atomicAdd(&g_bar_cnt, 1u);
}
__device__ __forceinline__ void bar_wait(unsigned target, int tid) {
    if (tid == 0) {
        while (*(volatile unsigned *)&g_bar_cnt < target) {}
        __threadfence();
    }
    nbar();
}

__device__ void lstm_path(char *smraw) {
    const int tid = threadIdx.x, lane = tid & 31, wid = tid >> 5;
    if (wid >= 4) return;
    __half *Ws1 = (__half *)smraw;                 // [16][520]
    __half *Ws2a = Ws1 + 16 * 520;
    __half *Ws2b = Ws2a + 16 * 520;
    __half *As = Ws2b + 16 * 520;                  // [2][64][136]
    float *zs = (float *)(As + 2 * 64 * 136);      // [64][17]
    float *cs1 = zs + 64 * 17;                     // [256]
    float *cs2 = cs1 + 256;

    const int wm = wid & 1, wn = wid >> 1;
    const int u0 = blockIdx.x * 4;

    for (int q = tid; q < 16 * 64; q += 128) {
        int r = q >> 6, c8 = q & 63;
        size_t grow = (size_t)((r >> 2) * 512 + u0 + (r & 3)) * 512;
        *(uint4 *)&Ws1[r * 520 + c8 * 8] = *(const uint4 *)(g_whh1 + grow + c8 * 8);
        *(uint4 *)&Ws2a[r * 520 + c8 * 8] = *(const uint4 *)(g_wih2h + grow + c8 * 8);
        *(uint4 *)&Ws2b[r * 520 + c8 * 8] = *(const uint4 *)(g_whh2h + grow + c8 * 8);
    }
    for (int q = tid; q < 256; q += 128) { cs1[q] = 0.f; cs2[q] = 0.f; }
    nbar();

    unsigned tgt = 0;
    for (int t = 0; t < LDEC; t++) {
        int cur = t & 1, nxt = cur ^ 1;
        float acc[2][4];
#pragma unroll
        for (int i = 0; i < 2; i++)
#pragma unroll
            for (int e = 0; e < 4; e++) acc[i][e] = 0.f;

        lstm_mm(acc, &g_h1[cur][0], Ws1, As, tid, lane, wm, wn);
        store_zs(acc, zs, lane, wm, wn);
        if (tid == 0) {
            while (*(volatile int *)&g_k5done[t >> 1] < 16) __nanosleep(64);
            __threadfence();
        }
        nbar();
#pragma unroll
        for (int i = 0; i < 2; i++) {
            int idx = tid + i * 128;
            int n = idx & 63, ul = idx >> 6;
            float zi = zs[n * 17 + ul], zf = zs[n * 17 + 4 + ul];
            float zg = zs[n * 17 + 8 + ul], zo = zs[n * 17 + 12 + ul];
            int u = u0 + ul;
            const float *zr = g_Zin1 + ((size_t)t * 64 + n) * 2048;
            zi += zr[u]; zf += zr[512 + u]; zg += zr[1024 + u]; zo += zr[1536 + u];
            float c = cs1[n * 4 + ul];
            float ig = 1.f / (1.f + expf(-zi));
            float fg = 1.f / (1.f + expf(-zf));
            float og = 1.f / (1.f + expf(-zo));
            float cn = fg * c + ig * tanhf(zg);
            float h = og * tanhf(cn);
            cs1[n * 4 + ul] = cn;
            __stcg(&g_h1[nxt][n * 512 + u], __float2half(h));
        }
        bar_arrive(tid); tgt++;
        unsigned tA = tgt;

#pragma unroll
        for (int i = 0; i < 2; i++)
#pragma unroll
            for (int e = 0; e < 4; e++) acc[i][e] = 0.f;
        if (t > 0) bar_wait((tgt - 1) * LSTM_BLOCKS, tid);
        lstm_mm(acc, &g_h2[cur][0], Ws2b, As, tid, lane, wm, wn);
        bar_wait(tA * LSTM_BLOCKS, tid);
        lstm_mm(acc, &g_h1[nxt][0], Ws2a, As, tid, lane, wm, wn);
        store_zs(acc, zs, lane, wm, wn);
#pragma unroll
        for (int i = 0; i < 2; i++) {
            int idx = tid + i * 128;
            int n = idx & 63, ul = idx >> 6;
            float zi = zs[n * 17 + ul], zf = zs[n * 17 + 4 + ul];
            float zg = zs[n * 17 + 8 + ul], zo = zs[n * 17 + 12 + ul];
            int u = u0 + ul;
            zi += g_b2[u]; zf += g_b2[512 + u]; zg += g_b2[1024 + u]; zo += g_b2[1536 + u];
            float c = cs2[n * 4 + ul];
            float ig = 1.f / (1.f + expf(-zi));
            float fg = 1.f / (1.f + expf(-zf));
            float og = 1.f / (1.f + expf(-zo));
            float cn = fg * c + ig * tanhf(zg);
            float h = og * tanhf(cn);
            cs2[n * 4 + ul] = cn;
            __stcg(&g_h2[nxt][n * 512 + u], __float2half(h));
            g_A7[((size_t)t * 64 + n) * 1024 + u] = __float2half(h);
        }
        bar_arrive(tid); tgt++;
    }
}

// ---------------- K7 worker ----------------
__device__ __noinline__ void worker_k7(__half *smh, float *out, const float *b_out) {
    __half *As = smh;
    __half *Bs = smh + 3 * 8192;
    __shared__ int s_q7;
    const int tid = threadIdx.x, lane = tid & 31, wid = tid >> 5;
    for (;;) {
        __syncthreads();
        if (tid == 0) s_q7 = atomicAdd(&g_q7, 1);
        __syncthreads();
        int q = s_q7;
        if (q >= K7_TILES) break;
        int mx = q / K7_NT, ny = q % K7_NT;
        if (tid == 0) {
            unsigned need = (4u * mx + 4u) * LSTM_BLOCKS;
            while (*(volatile unsigned *)&g_bar_cnt < need) __nanosleep(64);
            __threadfence();
        }
        __syncthreads();
        do_tile(g_A7, 1024, g_wout, 1024, 16, out, nullptr, b_out, NVOC,
                mx * 128, ny * 128, 6, 63, NVOC, (long long)LDEC * NVOC,
                As, Bs, tid, lane, wid);
    }
}

// ============ mega kernel: softmax + K4 + K5 + LSTM + K7 ============
__global__ void __launch_bounds__(256, 2) mega_k(float *out, const float *b_out,
                                                 const int *lens) {
    extern __shared__ __half smh[];
    __half *As = smh;
    __half *Bs = smh + 3 * 8192;
    __shared__ int s_q;
    const int tid = threadIdx.x, lane = tid & 31, wid = tid >> 5;

    // ---- phase S: masked softmax (128 chunks of 128 rows) ----
    for (;;) {
        __syncthreads();
        if (tid == 0) s_q = atomicAdd(&g_qS, 1);
        __syncthreads();
        int c = s_q;
        if (c >= 128) break;
        int n = c >> 1;
        int len = lens[n];
        size_t base = (size_t)n * 256 + (size_t)(c & 1) * 128;
        for (int r = wid; r < 128; r += 8) {
            const float *e = g_E + (base + r) * 512;
            float v[16], m = -1e30f;
#pragma unroll
            for (int i = 0; i < 16; i++) {
                v[i] = e[lane + i * 32];
                m = fmaxf(m, v[i]);
            }
#pragma unroll
            for (int o = 16; o; o >>= 1) m = fmaxf(m, __shfl_xor_sync(0xffffffffu, m, o));
            float s = 0.f;
#pragma unroll
            for (int i = 0; i < 16; i++) {
                int t = lane + i * 32;
                float ex = (t < len) ? expf(v[i] - m) : 0.f;
                v[i] = ex;
                s += ex;
            }
#pragma unroll
            for (int o = 16; o; o >>= 1) s += __shfl_xor_sync(0xffffffffu, s, o);
            float inv = 1.f / s;
            __half *ao = g_att + (base + r) * 512;
#pragma unroll
            for (int i = 0; i < 16; i++) ao[lane + i * 32] = __float2half(v[i] * inv);
        }
        __threadfence();
        __syncthreads();
        if (tid == 0) atomicExch(&g_doneS[c], 1);
    }

    // ---- phase K4: mx-major so done4[0] completes early ----
    for (;;) {
        __syncthreads();
        if (tid == 0) s_q = atomicAdd(&g_q4, 1);
        __syncthreads();
        int q = s_q;
        if (q >= 512) break;
        int mx = q >> 8, n = (q >> 2) & 63, ny = q & 3;
        if (tid == 0) {
            while (*(volatile int *)&g_doneS[n * 2 + mx] == 0) __nanosleep(64);
            __threadfence();
        }
        __syncthreads();
        do_tile(g_att + (size_t)n * 131072, 512, g_valT + (size_t)n * 262144, 512, 8,
                nullptr, g_Ain + (size_t)n * 1024 + 512, nullptr, 512,
                mx * 128, ny * 128, 0, 0, 65536, 0, As, Bs, tid, lane, wid);
        __threadfence();
        __syncthreads();
        if (tid == 0) atomicAdd(&g_done4[mx], 1);
    }

    if (blockIdx.x < LSTM_BLOCKS) {
        lstm_path((char *)smh);
        __syncthreads();
        worker_k7(smh, out, b_out);
    } else {
        // ---- K5: Zin1 = Ain @ wih1^T + b1, gated on K4 halves ----
        for (;;) {
            __syncthreads();
            if (tid == 0) s_q = atomicAdd(&g_q5, 1);
            __syncthreads();
            int q = s_q;
            if (q >= K5_TILES) break;
            int mx = q >> 4, ny = q & 15;
            if (tid == 0) {
                while (*(volatile int *)&g_done4[mx >> 6] < 256) __nanosleep(64);
                __threadfence();
            }
            __syncthreads();
            do_tile(g_Ain, 1024, g_wih1, 1024, 16, g_Zin1, nullptr, g_b1, 2048,
                    mx * 128, ny * 128, 0, 0, 2048, 0, As, Bs, tid, lane, wid);
            __threadfence();
            __syncthreads();
            if (tid == 0) atomicAdd(&g_k5done[mx], 1);
        }
        worker_k7(smh, out, b_out);
    }
}

// ============ K2: energy E[(n,l),t] = CE . key ============
__global__ void __launch_bounds__(256, 2) k2_k() {
    extern __shared__ __half smh[];
    const int b = blockIdx.x, tid = threadIdx.x, lane = tid & 31, wid = tid >> 5;
    int n = b >> 3, mx = (b >> 2) & 1, ny = b & 3;
    do_tile(g_Ain + (size_t)n * 1024, 65536, g_keyh + (size_t)n * 512, 32768, 8,
            g_E + (size_t)n * 131072, nullptr, nullptr, 512,
            mx * 128, ny * 128, 0, 0, 512, 0,
            smh, smh + 3 * 8192, tid, lane, wid);
}

// ============ prep ============
__device__ __forceinline__ void f2h_seg(const float *s, __half *d, int n8,
                                        int gt, int gs) {
    const float4 *s4 = (const float4 *)s;
    uint4 *d4 = (uint4 *)d;
    for (int i = gt; i < n8; i += gs) {
        float4 a = s4[i * 2], b = s4[i * 2 + 1];
        __half2 h0 = __floats2half2_rn(a.x, a.y);
        __half2 h1 = __floats2half2_rn(a.z, a.w);
        __half2 h2 = __floats2half2_rn(b.x, b.y);
        __half2 h3 = __floats2half2_rn(b.z, b.w);
        d4[i] = make_uint4(*(uint32_t *)&h0, *(uint32_t *)&h1,
                           *(uint32_t *)&h2, *(uint32_t *)&h3);
    }
}

__global__ void prep_k(const float *key, const int *text, const float *emb,
                       const float *b_ih1, const float *b_hh1,
                       const float *b_ih2, const float *b_hh2,
                       const float *w_ih1, const float *w_hh1,
                       const float *w_ih2, const float *w_hh2,
                       const float *w_out, const float *values) {
    __shared__ float tile[32][33];
    const int gt = blockIdx.x * 256 + threadIdx.x;
    const int gs = gridDim.x * 256;

    f2h_seg(key, g_keyh, 2097152, gt, gs);
    f2h_seg(w_ih1, g_wih1, 262144, gt, gs);
    f2h_seg(w_hh1, g_whh1, 131072, gt, gs);
    f2h_seg(w_ih2, g_wih2h, 131072, gt, gs);
    f2h_seg(w_hh2, g_whh2h, 131072, gt, gs);
    f2h_seg(w_out, g_wout, 1280000, gt, gs);

    for (int j = gt; j < 2097152; j += gs) {
        int k4 = (j & 127) * 4;
        int r = j >> 7;
        int n = r & 63, l = r >> 6;
        int tok = text[n * LDEC + l];
        float4 v = *(const float4 *)(emb + (size_t)tok * 512 + k4);
        __half2 h0 = __floats2half2_rn(v.x, v.y);
        __half2 h1 = __floats2half2_rn(v.z, v.w);
        *(uint2 *)(g_Ain + (size_t)r * 1024 + k4) =
            make_uint2(*(uint32_t *)&h0, *(uint32_t *)&h1);
    }
    for (int j = gt; j < 1048576; j += gs) {
        int e8 = j * 8;
        int col = e8 & 511;
        int r = e8 >> 9;
        int n = r & 63, l = r >> 6;
        const float4 *s = (const float4 *)(values + (size_t)l * 32768 + n * 512 + col);
        float4 a = s[0], b = s[1];
        __half2 h0 = __floats2half2_rn(a.x, a.y);
        __half2 h1 = __floats2half2_rn(a.z, a.w);
        __half2 h2 = __floats2half2_rn(b.x, b.y);
        __half2 h3 = __floats2half2_rn(b.z, b.w);
        *(uint4 *)(g_A7 + (size_t)r * 1024 + 512 + col) =
            make_uint4(*(uint32_t *)&h0, *(uint32_t *)&h1,
                       *(uint32_t *)&h2, *(uint32_t *)&h3);
    }
    for (int j = gt; j < 2048; j += gs) {
        g_b1[j] = b_ih1[j] + b_hh1[j];
        g_b2[j] = b_ih2[j] + b_hh2[j];
    }
    for (int j = gt; j < NB * 512; j += gs) {
        g_h1[0][j] = __ushort_as_half((unsigned short)0);
        g_h2[0][j] = __ushort_as_half((unsigned short)0);
    }
    if (gt == 0) {
        g_bar_cnt = 0; g_qS = 0; g_q4 = 0; g_q5 = 0; g_q7 = 0;
        g_done4[0] = 0; g_done4[1] = 0;
    }
    for (int j = gt; j < 128; j += gs) { g_k5done[j] = 0; g_doneS[j] = 0; }

    const int tx = threadIdx.x & 31, ty = threadIdx.x >> 5;
    for (int t = blockIdx.x; t < 16384; t += gridDim.x) {
        int n = t >> 8, vb = (t >> 4) & 15, tb = t & 15;
        int t0 = tb * 32, v0 = vb * 32;
        __syncthreads();
#pragma unroll
        for (int i = 0; i < 4; i++)
            tile[ty + i * 8][tx] =
                values[(size_t)(t0 + ty + i * 8) * 32768 + n * 512 + v0 + tx];
        __syncthreads();
#pragma unroll
        for (int i = 0; i < 4; i++)
            g_valT[((size_t)n * 512 + v0 + ty + i * 8) * 512 + t0 + tx] =
                __float2half(tile[tx][ty + i * 8]);
    }
}

// ---------------- host ----------------
static const int GEMM_SMEM = 3 * (8192 + 8192) * 2;  // 96 KB

extern "C" void kernel_launch(void *const *d_in, const int *in_sizes, int n_in,
                              void *d_out, int out_size) {
    const float *key = (const float *)d_in[0];
    const float *values = (const float *)d_in[1];
    const int *text = (const int *)d_in[2];
    const int *text_lens = (const int *)d_in[3];
    const float *emb = (const float *)d_in[4];
    const float *w_ih1 = (const float *)d_in[5];
    const float *w_hh1 = (const float *)d_in[6];
    const float *b_ih1 = (const float *)d_in[7];
    const float *b_hh1 = (const float *)d_in[8];
    const float *w_ih2 = (const float *)d_in[9];
    const float *w_hh2 = (const float *)d_in[10];
    const float *b_ih2 = (const float *)d_in[11];
    const float *b_hh2 = (const float *)d_in[12];
    const float *w_out = (const float *)d_in[13];
    const float *b_out = (const float *)d_in[14];
    float *out = (float *)d_out;

    cudaFuncSetAttribute(k2_k, cudaFuncAttributeMaxDynamicSharedMemorySize, GEMM_SMEM);
    cudaFuncSetAttribute(mega_k, cudaFuncAttributeMaxDynamicSharedMemorySize, GEMM_SMEM);

    // 1) all prep in one launch
    prep_k<<<2048, 256>>>(key, text, emb, b_ih1, b_hh1, b_ih2, b_hh2,
                          w_ih1, w_hh1, w_ih2, w_hh2, w_out, values);

    // 2) K2 energy GEMM (full-chip wave)
    k2_k<<<512, 256, GEMM_SMEM>>>();

    // 3) mega: softmax + K4 + K5 + persistent LSTM + K7
    mega_k<<<LSTM_BLOCKS + N_WORKERS, 256, GEMM_SMEM>>>(out, b_out, text_lens);
}